// round 4
// baseline (speedup 1.0000x reference)
#include <cuda_runtime.h>

typedef unsigned long long ull;

// Transposed weights in global (built once per replay by setup_kernel).
__device__ float g_WT[2][256 * 64];    // [k][c]  (0: Wfp1, 1: Wf1)
__device__ float g_WngTd[128 * 128];   // [k][2c] duplicated pairs

__global__ void setup_kernel(const float* __restrict__ Wfp1,
                             const float* __restrict__ Wf1,
                             const float* __restrict__ Wng) {
    int tid = blockIdx.x * blockDim.x + threadIdx.x;
    int stride = gridDim.x * blockDim.x;
    for (int i = tid; i < 256 * 64; i += stride) {
        int k = i >> 6, c = i & 63;
        g_WT[0][i] = Wfp1[c * 256 + k];
        g_WT[1][i] = Wf1[c * 256 + k];
    }
    for (int i = tid; i < 128 * 64; i += stride) {
        int k = i >> 6, c = i & 63;
        float w = Wng[c * 128 + k];
        g_WngTd[k * 128 + 2 * c] = w;
        g_WngTd[k * 128 + 2 * c + 1] = w;
    }
}

__device__ __forceinline__ float sigmoidf_(float x) {
    return __fdividef(1.0f, 1.0f + __expf(-x));
}
__device__ __forceinline__ float gatef_(float x, float rm) {
    return x * sigmoidf_(fabsf(x - rm));
}
__device__ __forceinline__ float leakyf_(float x) {
    return x > 0.0f ? x : 0.01f * x;
}
__device__ __forceinline__ void ffma2_(ull& d, ull a, ull b) {
    asm("fma.rn.f32x2 %0, %1, %2, %0;" : "+l"(d) : "l"(a), "l"(b));
}
__device__ __forceinline__ ull fmul2_(ull a, ull b) {
    ull r;
    asm("mul.rn.f32x2 %0, %1, %2;" : "=l"(r) : "l"(a), "l"(b));
    return r;
}
__device__ __forceinline__ float2 unpk_(ull v) {
    float2 r;
    asm("mov.b64 {%0, %1}, %2;" : "=f"(r.x), "=f"(r.y) : "l"(v));
    return r;
}

// Matvecs + sigmoid + pooling for one branch, inputs read from global.
// Thread (r, q): outputs j = 4q..4q+3 of 3 modalities for row r.
// Writes pooled factors transposed: sMx[ix][r], sM2y[iy][r], sMz[iz][r].
__device__ __forceinline__ void stage_factors(
    const float* __restrict__ x, const float* __restrict__ y,
    const float* __restrict__ z, int row,
    float* __restrict__ sMx, float* __restrict__ sM2y,
    float* __restrict__ sMz,
    const float* __restrict__ Wx, const float* __restrict__ bx,
    const float* __restrict__ Wy, const float* __restrict__ by,
    const float* __restrict__ Wz, const float* __restrict__ bz,
    int r, int q) {
    float a0[4], a1[4], a2[4];
#pragma unroll
    for (int jj = 0; jj < 4; jj++) {
        a0[jj] = __ldg(bx + q * 4 + jj);
        a1[jj] = __ldg(by + q * 4 + jj);
        a2[jj] = __ldg(bz + q * 4 + jj);
    }
#pragma unroll 4
    for (int k = 0; k < 64; k += 4) {
        float4 x0 = __ldg(reinterpret_cast<const float4*>(x + row * 64 + k));
        float4 x1 = __ldg(reinterpret_cast<const float4*>(y + row * 64 + k));
        float4 x2 = __ldg(reinterpret_cast<const float4*>(z + row * 64 + k));
#pragma unroll
        for (int jj = 0; jj < 4; jj++) {
            int woff = (q * 4 + jj) * 64 + k;
            float4 w0 = __ldg(reinterpret_cast<const float4*>(Wx + woff));
            a0[jj] = fmaf(x0.x, w0.x, a0[jj]); a0[jj] = fmaf(x0.y, w0.y, a0[jj]);
            a0[jj] = fmaf(x0.z, w0.z, a0[jj]); a0[jj] = fmaf(x0.w, w0.w, a0[jj]);
            float4 w1 = __ldg(reinterpret_cast<const float4*>(Wy + woff));
            a1[jj] = fmaf(x1.x, w1.x, a1[jj]); a1[jj] = fmaf(x1.y, w1.y, a1[jj]);
            a1[jj] = fmaf(x1.z, w1.z, a1[jj]); a1[jj] = fmaf(x1.w, w1.w, a1[jj]);
            float4 w2 = __ldg(reinterpret_cast<const float4*>(Wz + woff));
            a2[jj] = fmaf(x2.x, w2.x, a2[jj]); a2[jj] = fmaf(x2.y, w2.y, a2[jj]);
            a2[jj] = fmaf(x2.z, w2.z, a2[jj]); a2[jj] = fmaf(x2.w, w2.w, a2[jj]);
        }
    }
    float hx[4], hy[4], hz[4];
#pragma unroll
    for (int jj = 0; jj < 4; jj++) {
        hx[jj] = sigmoidf_(a0[jj]);
        hy[jj] = sigmoidf_(a1[jj]);
        hz[jj] = sigmoidf_(a2[jj]);
    }
    sMx[(2 * q) * 64 + r] = fmaxf(hx[0], hx[1]);
    sMx[(2 * q + 1) * 64 + r] = fmaxf(hx[2], hx[3]);
    sM2y[q * 64 + r] = fmaxf(fmaxf(hy[0], hy[1]), fmaxf(hy[2], hy[3]));
    sMz[(2 * q) * 64 + r] = fmaxf(hz[0], hz[1]);
    sMz[(2 * q + 1) * 64 + r] = fmaxf(hz[2], hz[3]);
}

// Build duplicated P / mz tables from raw pooled factors.
__device__ __forceinline__ void build_dup(
    const float* __restrict__ sMx, const float* __restrict__ sM2y,
    const float* __restrict__ sMz, float* __restrict__ sPd,
    float* __restrict__ sMzd, int tid) {
#pragma unroll
    for (int it = 0; it < 8; it++) {
        int i = tid + it * 256;  // 32*64
        int u = i >> 6, r = i & 63;
        float p = sMx[(u >> 2) * 64 + r] * sM2y[(u & 3) * 64 + r];
        *reinterpret_cast<float2*>(sPd + u * 128 + 2 * r) = make_float2(p, p);
    }
#pragma unroll
    for (int it = 0; it < 2; it++) {
        int i = tid + it * 256;  // 8*64
        int t = i >> 6, r = i & 63;
        float m = sMz[t * 64 + r];
        *reinterpret_cast<float2*>(sMzd + t * 128 + 2 * r) = make_float2(m, m);
    }
}

// Fusion GEMM: out[r][c] = sum_k (P[r][k>>3]*mz[r][k&7]) * WT[k][c].
// Thread tile: 2 rows (r0, r0+1) x 8 cols (c0..c0+7), col-pair packed accs.
__device__ __forceinline__ void gemm_fuse(
    const float* __restrict__ sPd, const float* __restrict__ sMzd,
    const float* __restrict__ gW, int r0, int c0, ull acc[2][4]) {
    ull mz2[2][8];
#pragma unroll
    for (int t = 0; t < 8; t++) {
        ulonglong2 m = *reinterpret_cast<const ulonglong2*>(sMzd + t * 128 + 2 * r0);
        mz2[0][t] = m.x;
        mz2[1][t] = m.y;
    }
#pragma unroll 2
    for (int u = 0; u < 32; u++) {
        ulonglong2 pu = *reinterpret_cast<const ulonglong2*>(sPd + u * 128 + 2 * r0);
        const float* wrow = gW + u * 8 * 64 + c0;
#pragma unroll
        for (int t = 0; t < 8; t++) {
            ulonglong2 w0 = __ldg(reinterpret_cast<const ulonglong2*>(wrow + t * 64));
            ulonglong2 w1 = __ldg(reinterpret_cast<const ulonglong2*>(wrow + t * 64 + 4));
            ull f0 = fmul2_(pu.x, mz2[0][t]);
            ull f1 = fmul2_(pu.y, mz2[1][t]);
            ffma2_(acc[0][0], f0, w0.x); ffma2_(acc[0][1], f0, w0.y);
            ffma2_(acc[0][2], f0, w1.x); ffma2_(acc[0][3], f0, w1.y);
            ffma2_(acc[1][0], f1, w0.x); ffma2_(acc[1][1], f1, w0.y);
            ffma2_(acc[1][2], f1, w1.x); ffma2_(acc[1][3], f1, w1.y);
        }
    }
}

// Shared layout (floats)
#define OFF_GT 0            // [128][66] = 8448
#define OFF_PD 8448         // [32][128] = 4096
#define OFF_MZD 12544       // [8][128]  = 1024
#define OFF_MX 13568        // [8][64]
#define OFF_M2Y 14080       // [4][64]
#define OFF_MZ 14336        // [8][64]
#define SMEM_FLOATS 14848

__global__ void __launch_bounds__(256, 3) fusion_main(
    const float* __restrict__ a, const float* __restrict__ v,
    const float* __restrict__ l, const float* __restrict__ pa,
    const float* __restrict__ pv, const float* __restrict__ pl,
    const float* __restrict__ mean,
    const float* __restrict__ Wa, const float* __restrict__ ba,
    const float* __restrict__ Wv, const float* __restrict__ bv,
    const float* __restrict__ Wl, const float* __restrict__ bl,
    const float* __restrict__ Wap, const float* __restrict__ bap,
    const float* __restrict__ Wvp, const float* __restrict__ bvp,
    const float* __restrict__ Wlp, const float* __restrict__ blp,
    const float* __restrict__ bf1, const float* __restrict__ bfp1,
    const float* __restrict__ bng, const float* __restrict__ rm1,
    const float* __restrict__ rm2, float* __restrict__ out) {
    extern __shared__ __align__(16) float smem[];
    float* sGT = smem + OFF_GT;
    float* sPd = smem + OFF_PD;
    float* sMzd = smem + OFF_MZD;
    float* sMx = smem + OFF_MX;
    float* sM2y = smem + OFF_M2Y;
    float* sMz = smem + OFF_MZ;

    const int tid = threadIdx.x;
    const int row0 = blockIdx.x * 64;
    const int r = tid >> 2, q = tid & 3;   // factors mapping
    const int r0 = (tid >> 3) * 2;         // GEMM row base
    const int c0 = (tid & 7) * 8;          // GEMM col base

    // ---- S0: fusion-2 factors; gated mean -> sGT rows 64..127 ----
    stage_factors(pa, pv, pl, row0 + r, sMx, sM2y, sMz,
                  Wap, bap, Wvp, bvp, Wlp, blp, r, q);
#pragma unroll
    for (int it = 0; it < 16; it++) {
        int i = tid + it * 256;          // 4096
        int rr = i >> 6, c = i & 63;
        float m = __ldg(mean + (row0 + rr) * 64 + c);
        sGT[(64 + c) * 66 + rr] = gatef_(m, __ldg(rm1 + 64 + c));
    }
    __syncthreads();

    // ---- S1: build dup tables ----
    build_dup(sMx, sM2y, sMz, sPd, sMzd, tid);
    __syncthreads();

    // ---- S2: GEMM1 (K=256) -> gate -> sGT rows 0..63 ----
    {
        ull acc[2][4] = {};
        gemm_fuse(sPd, sMzd, g_WT[0], r0, c0, acc);
#pragma unroll
        for (int i = 0; i < 2; i++)
#pragma unroll
            for (int j = 0; j < 4; j++) {
                float2 p = unpk_(acc[i][j]);
                int ca = c0 + 2 * j, cb = ca + 1;
                sGT[ca * 66 + r0 + i] =
                    gatef_(leakyf_(p.x + __ldg(bfp1 + ca)), __ldg(rm1 + ca));
                sGT[cb * 66 + r0 + i] =
                    gatef_(leakyf_(p.y + __ldg(bfp1 + cb)), __ldg(rm1 + cb));
            }
    }
    __syncthreads();

    // ---- S3: GEMM2 (K=128, row-pair packed) -> out[:,0:64]; factors1 ----
    {
        ull acc2[8] = {};
#pragma unroll 4
        for (int k = 0; k < 128; k++) {
            ull f = *reinterpret_cast<const ull*>(sGT + k * 66 + r0);
            const float* wr = g_WngTd + k * 128 + 2 * c0;
            ulonglong2 wa = __ldg(reinterpret_cast<const ulonglong2*>(wr));
            ulonglong2 wb = __ldg(reinterpret_cast<const ulonglong2*>(wr + 4));
            ulonglong2 wc = __ldg(reinterpret_cast<const ulonglong2*>(wr + 8));
            ulonglong2 wd = __ldg(reinterpret_cast<const ulonglong2*>(wr + 12));
            ffma2_(acc2[0], f, wa.x); ffma2_(acc2[1], f, wa.y);
            ffma2_(acc2[2], f, wb.x); ffma2_(acc2[3], f, wb.y);
            ffma2_(acc2[4], f, wc.x); ffma2_(acc2[5], f, wc.y);
            ffma2_(acc2[6], f, wd.x); ffma2_(acc2[7], f, wd.y);
        }
        float og0[8], og1[8];
#pragma unroll
        for (int j = 0; j < 8; j++) {
            int c = c0 + j;
            float2 p = unpk_(acc2[j]);  // rows r0, r0+1
            float bb = __ldg(bng + c), rr2 = __ldg(rm2 + c);
            og0[j] = gatef_(p.x + bb, rr2);
            og1[j] = gatef_(p.y + bb, rr2);
        }
        *reinterpret_cast<float4*>(out + (row0 + r0) * 128 + c0) =
            make_float4(og0[0], og0[1], og0[2], og0[3]);
        *reinterpret_cast<float4*>(out + (row0 + r0) * 128 + c0 + 4) =
            make_float4(og0[4], og0[5], og0[6], og0[7]);
        *reinterpret_cast<float4*>(out + (row0 + r0 + 1) * 128 + c0) =
            make_float4(og1[0], og1[1], og1[2], og1[3]);
        *reinterpret_cast<float4*>(out + (row0 + r0 + 1) * 128 + c0 + 4) =
            make_float4(og1[4], og1[5], og1[6], og1[7]);
    }
    stage_factors(a, v, l, row0 + r, sMx, sM2y, sMz,
                  Wa, ba, Wv, bv, Wl, bl, r, q);
    __syncthreads();

    // ---- S4: build dup tables (fusion 1) ----
    build_dup(sMx, sM2y, sMz, sPd, sMzd, tid);
    __syncthreads();

    // ---- S5: GEMM3 (K=256) -> out[:,64:128] ----
    {
        ull acc[2][4] = {};
        gemm_fuse(sPd, sMzd, g_WT[1], r0, c0, acc);
#pragma unroll
        for (int i = 0; i < 2; i++) {
            float og[8];
#pragma unroll
            for (int j = 0; j < 4; j++) {
                float2 p = unpk_(acc[i][j]);
                int ca = c0 + 2 * j, cb = ca + 1;
                og[2 * j] =
                    gatef_(leakyf_(p.x + __ldg(bf1 + ca)), __ldg(rm2 + 64 + ca));
                og[2 * j + 1] =
                    gatef_(leakyf_(p.y + __ldg(bf1 + cb)), __ldg(rm2 + 64 + cb));
            }
            float* orow = out + (row0 + r0 + i) * 128 + 64 + c0;
            *reinterpret_cast<float4*>(orow) =
                make_float4(og[0], og[1], og[2], og[3]);
            *reinterpret_cast<float4*>(orow + 4) =
                make_float4(og[4], og[5], og[6], og[7]);
        }
    }
}

extern "C" void kernel_launch(void* const* d_in, const int* in_sizes, int n_in,
                              void* d_out, int out_size) {
    const float* a    = (const float*)d_in[0];
    const float* v    = (const float*)d_in[1];
    const float* l    = (const float*)d_in[2];
    const float* pa   = (const float*)d_in[3];
    const float* pv   = (const float*)d_in[4];
    const float* pl   = (const float*)d_in[5];
    const float* mean = (const float*)d_in[6];
    const float* Wa   = (const float*)d_in[7];
    const float* ba   = (const float*)d_in[8];
    const float* Wv   = (const float*)d_in[9];
    const float* bv   = (const float*)d_in[10];
    const float* Wl   = (const float*)d_in[11];
    const float* bl   = (const float*)d_in[12];
    const float* Wap  = (const float*)d_in[13];
    const float* bap  = (const float*)d_in[14];
    const float* Wvp  = (const float*)d_in[15];
    const float* bvp  = (const float*)d_in[16];
    const float* Wlp  = (const float*)d_in[17];
    const float* blp  = (const float*)d_in[18];
    const float* Wf1  = (const float*)d_in[19];
    const float* bf1  = (const float*)d_in[20];
    const float* Wfp1 = (const float*)d_in[21];
    const float* bfp1 = (const float*)d_in[22];
    const float* Wng  = (const float*)d_in[23];
    const float* bng  = (const float*)d_in[24];
    const float* rm1  = (const float*)d_in[25];
    const float* rm2  = (const float*)d_in[26];

    int nrows = in_sizes[0] / 64;
    static int smem_set = 0;
    if (!smem_set) {
        cudaFuncSetAttribute(fusion_main,
                             cudaFuncAttributeMaxDynamicSharedMemorySize,
                             SMEM_FLOATS * 4);
        smem_set = 1;
    }

    setup_kernel<<<64, 256>>>(Wfp1, Wf1, Wng);
    fusion_main<<<nrows / 64, 256, SMEM_FLOATS * 4>>>(
        a, v, l, pa, pv, pl, mean,
        Wa, ba, Wv, bv, Wl, bl,
        Wap, bap, Wvp, bvp, Wlp, blp,
        bf1, bfp1, bng, rm1, rm2, (float*)d_out);
}

// round 5
// speedup vs baseline: 1.1440x; 1.1440x over previous
#include <cuda_runtime.h>

typedef unsigned long long ull;

// Transposed weights in global (built once per replay by setup kernel).
__device__ float g_WT[2][256 * 64];    // [k][c]  (0: Wfp1, 1: Wf1)
__device__ float g_WngTd[128 * 128];   // [k][2c] duplicated pairs

__global__ void setup_kernel(const float* __restrict__ Wfp1,
                             const float* __restrict__ Wf1,
                             const float* __restrict__ Wng) {
    int tid = blockIdx.x * blockDim.x + threadIdx.x;
    int stride = gridDim.x * blockDim.x;
    for (int i = tid; i < 256 * 64; i += stride) {
        int k = i >> 6, c = i & 63;
        g_WT[0][i] = Wfp1[c * 256 + k];
        g_WT[1][i] = Wf1[c * 256 + k];
    }
    for (int i = tid; i < 128 * 64; i += stride) {
        int k = i >> 6, c = i & 63;
        float w = Wng[c * 128 + k];
        g_WngTd[k * 128 + 2 * c] = w;
        g_WngTd[k * 128 + 2 * c + 1] = w;
    }
}

__device__ __forceinline__ float sigmoidf_(float x) {
    return __fdividef(1.0f, 1.0f + __expf(-x));
}
__device__ __forceinline__ float gatef_(float x, float rm) {
    return x * sigmoidf_(fabsf(x - rm));
}
__device__ __forceinline__ float leakyf_(float x) {
    return x > 0.0f ? x : 0.01f * x;
}
__device__ __forceinline__ void ffma2_(ull& d, ull a, ull b) {
    asm("fma.rn.f32x2 %0, %1, %2, %0;" : "+l"(d) : "l"(a), "l"(b));
}
__device__ __forceinline__ ull fmul2_(ull a, ull b) {
    ull r;
    asm("mul.rn.f32x2 %0, %1, %2;" : "=l"(r) : "l"(a), "l"(b));
    return r;
}
__device__ __forceinline__ float2 unpk_(ull v) {
    float2 r;
    asm("mov.b64 {%0, %1}, %2;" : "=f"(r.x), "=f"(r.y) : "l"(v));
    return r;
}

// Matvecs + sigmoid + pooling; writes factors DIRECTLY duplicated ({x,x}
// pairs) into sMxd[8][128], sM2yd[4][128], sMzd[8][128] at column 2r.
__device__ __forceinline__ void stage_factors(
    const float* __restrict__ x, const float* __restrict__ y,
    const float* __restrict__ z, int row,
    float* __restrict__ sMxd, float* __restrict__ sM2yd,
    float* __restrict__ sMzd,
    const float* __restrict__ Wx, const float* __restrict__ bx,
    const float* __restrict__ Wy, const float* __restrict__ by,
    const float* __restrict__ Wz, const float* __restrict__ bz,
    int r, int q) {
    float a0[4], a1[4], a2[4];
#pragma unroll
    for (int jj = 0; jj < 4; jj++) {
        a0[jj] = __ldg(bx + q * 4 + jj);
        a1[jj] = __ldg(by + q * 4 + jj);
        a2[jj] = __ldg(bz + q * 4 + jj);
    }
#pragma unroll 4
    for (int k = 0; k < 64; k += 4) {
        float4 x0 = __ldg(reinterpret_cast<const float4*>(x + row * 64 + k));
        float4 x1 = __ldg(reinterpret_cast<const float4*>(y + row * 64 + k));
        float4 x2 = __ldg(reinterpret_cast<const float4*>(z + row * 64 + k));
#pragma unroll
        for (int jj = 0; jj < 4; jj++) {
            int woff = (q * 4 + jj) * 64 + k;
            float4 w0 = __ldg(reinterpret_cast<const float4*>(Wx + woff));
            a0[jj] = fmaf(x0.x, w0.x, a0[jj]); a0[jj] = fmaf(x0.y, w0.y, a0[jj]);
            a0[jj] = fmaf(x0.z, w0.z, a0[jj]); a0[jj] = fmaf(x0.w, w0.w, a0[jj]);
            float4 w1 = __ldg(reinterpret_cast<const float4*>(Wy + woff));
            a1[jj] = fmaf(x1.x, w1.x, a1[jj]); a1[jj] = fmaf(x1.y, w1.y, a1[jj]);
            a1[jj] = fmaf(x1.z, w1.z, a1[jj]); a1[jj] = fmaf(x1.w, w1.w, a1[jj]);
            float4 w2 = __ldg(reinterpret_cast<const float4*>(Wz + woff));
            a2[jj] = fmaf(x2.x, w2.x, a2[jj]); a2[jj] = fmaf(x2.y, w2.y, a2[jj]);
            a2[jj] = fmaf(x2.z, w2.z, a2[jj]); a2[jj] = fmaf(x2.w, w2.w, a2[jj]);
        }
    }
    float hx[4], hy[4], hz[4];
#pragma unroll
    for (int jj = 0; jj < 4; jj++) {
        hx[jj] = sigmoidf_(a0[jj]);
        hy[jj] = sigmoidf_(a1[jj]);
        hz[jj] = sigmoidf_(a2[jj]);
    }
    float mx0 = fmaxf(hx[0], hx[1]), mx1 = fmaxf(hx[2], hx[3]);
    float my = fmaxf(fmaxf(hy[0], hy[1]), fmaxf(hy[2], hy[3]));
    float mz0 = fmaxf(hz[0], hz[1]), mz1 = fmaxf(hz[2], hz[3]);
    *reinterpret_cast<float2*>(sMxd + (2 * q) * 128 + 2 * r) = make_float2(mx0, mx0);
    *reinterpret_cast<float2*>(sMxd + (2 * q + 1) * 128 + 2 * r) = make_float2(mx1, mx1);
    *reinterpret_cast<float2*>(sM2yd + q * 128 + 2 * r) = make_float2(my, my);
    *reinterpret_cast<float2*>(sMzd + (2 * q) * 128 + 2 * r) = make_float2(mz0, mz0);
    *reinterpret_cast<float2*>(sMzd + (2 * q + 1) * 128 + 2 * r) = make_float2(mz1, mz1);
}

// Fusion GEMM: out[r][c] = sum_k (mx[k>>5]*m2y[(k>>3)&3]*mz[k&7]) * WT[k][c].
// Thread tile: 2 rows (r0, r0+1) x 8 cols (c0..c0+7), col-pair packed accs.
// Weights from smem (sW, [256][64]); f built on the fly from dup tables.
__device__ __forceinline__ void gemm_fuse(
    const float* __restrict__ sW, const float* __restrict__ sMxd,
    const float* __restrict__ sM2yd, const float* __restrict__ sMzd,
    int r0, int c0, ull acc[2][4]) {
    ull mz2[2][8];
#pragma unroll
    for (int t = 0; t < 8; t++) {
        ulonglong2 m = *reinterpret_cast<const ulonglong2*>(sMzd + t * 128 + 2 * r0);
        mz2[0][t] = m.x;
        mz2[1][t] = m.y;
    }
#pragma unroll 2
    for (int ix = 0; ix < 8; ix++) {
        ulonglong2 mx2 = *reinterpret_cast<const ulonglong2*>(sMxd + ix * 128 + 2 * r0);
#pragma unroll
        for (int iy = 0; iy < 4; iy++) {
            ulonglong2 my2 = *reinterpret_cast<const ulonglong2*>(sM2yd + iy * 128 + 2 * r0);
            ull p0 = fmul2_(mx2.x, my2.x);
            ull p1 = fmul2_(mx2.y, my2.y);
            const float* wbase = sW + (ix * 4 + iy) * 8 * 64 + c0;
#pragma unroll
            for (int t = 0; t < 8; t++) {
                ulonglong2 w0 = *reinterpret_cast<const ulonglong2*>(wbase + t * 64);
                ulonglong2 w1 = *reinterpret_cast<const ulonglong2*>(wbase + t * 64 + 4);
                ull f0 = fmul2_(p0, mz2[0][t]);
                ull f1 = fmul2_(p1, mz2[1][t]);
                ffma2_(acc[0][0], f0, w0.x); ffma2_(acc[0][1], f0, w0.y);
                ffma2_(acc[0][2], f0, w1.x); ffma2_(acc[0][3], f0, w1.y);
                ffma2_(acc[1][0], f1, w0.x); ffma2_(acc[1][1], f1, w0.y);
                ffma2_(acc[1][2], f1, w1.x); ffma2_(acc[1][3], f1, w1.y);
            }
        }
    }
}

__device__ __forceinline__ void copy_w(float* __restrict__ dst,
                                       const float* __restrict__ src,
                                       int tid, int n4) {
    const float4* s = reinterpret_cast<const float4*>(src);
    float4* d = reinterpret_cast<float4*>(dst);
#pragma unroll
    for (int i = tid; i < n4; i += 256) d[i] = s[i];
}

// Shared layout (floats):
//  sW    @ 0     : 16384  (one weight region, reloaded per phase)
//  sGT   @ 16384 : 8448   ([128][66] gated concat)
//  sMxd  @ 24832 : 1024
//  sM2yd @ 25856 : 512
//  sMzd  @ 26368 : 1024
#define OFF_GT 16384
#define OFF_MXD 24832
#define OFF_M2YD 25856
#define OFF_MZD 26368
#define SMEM_FLOATS 27392

__global__ void __launch_bounds__(256, 2) fusion_main(
    const float* __restrict__ a, const float* __restrict__ v,
    const float* __restrict__ l, const float* __restrict__ pa,
    const float* __restrict__ pv, const float* __restrict__ pl,
    const float* __restrict__ mean,
    const float* __restrict__ Wa, const float* __restrict__ ba,
    const float* __restrict__ Wv, const float* __restrict__ bv,
    const float* __restrict__ Wl, const float* __restrict__ bl,
    const float* __restrict__ Wap, const float* __restrict__ bap,
    const float* __restrict__ Wvp, const float* __restrict__ bvp,
    const float* __restrict__ Wlp, const float* __restrict__ blp,
    const float* __restrict__ bf1, const float* __restrict__ bfp1,
    const float* __restrict__ bng, const float* __restrict__ rm1,
    const float* __restrict__ rm2, float* __restrict__ out) {
    extern __shared__ __align__(16) float smem[];
    float* sW = smem;
    float* sGT = smem + OFF_GT;
    float* sMxd = smem + OFF_MXD;
    float* sM2yd = smem + OFF_M2YD;
    float* sMzd = smem + OFF_MZD;

    const int tid = threadIdx.x;
    const int row0 = blockIdx.x * 64;
    const int r = tid >> 2, q = tid & 3;  // factor-stage mapping
    const int r0 = (tid >> 3) * 2;        // GEMM row base
    const int c0 = (tid & 7) * 8;         // GEMM col base

    // ---- P0: Wfp1T -> sW; fusion-2 factors; gated mean -> sGT[64..127] ----
    copy_w(sW, g_WT[0], tid, 4096);
    stage_factors(pa, pv, pl, row0 + r, sMxd, sM2yd, sMzd,
                  Wap, bap, Wvp, bvp, Wlp, blp, r, q);
#pragma unroll
    for (int it = 0; it < 16; it++) {
        int i = tid + it * 256;  // 4096
        int rr = i >> 6, c = i & 63;
        float m = __ldg(mean + (row0 + rr) * 64 + c);
        sGT[(64 + c) * 66 + rr] = gatef_(m, __ldg(rm1 + 64 + c));
    }
    __syncthreads();

    // ---- P1: GEMM1 (K=256) -> gate -> sGT rows 0..63 ----
    {
        ull acc[2][4] = {};
        gemm_fuse(sW, sMxd, sM2yd, sMzd, r0, c0, acc);
#pragma unroll
        for (int i = 0; i < 2; i++)
#pragma unroll
            for (int j = 0; j < 4; j++) {
                float2 p = unpk_(acc[i][j]);
                int ca = c0 + 2 * j, cb = ca + 1;
                sGT[ca * 66 + r0 + i] =
                    gatef_(leakyf_(p.x + __ldg(bfp1 + ca)), __ldg(rm1 + ca));
                sGT[cb * 66 + r0 + i] =
                    gatef_(leakyf_(p.y + __ldg(bfp1 + cb)), __ldg(rm1 + cb));
            }
    }
    __syncthreads();

    // ---- P2: WngTd -> sW; fusion-1 factors (overwrite dup tables) ----
    copy_w(sW, g_WngTd, tid, 4096);
    stage_factors(a, v, l, row0 + r, sMxd, sM2yd, sMzd,
                  Wa, ba, Wv, bv, Wl, bl, r, q);
    __syncthreads();

    // ---- P3: GEMM2 (K=128, row-pair packed) -> out[:,0:64] ----
    {
        ull acc2[8] = {};
#pragma unroll 4
        for (int k = 0; k < 128; k++) {
            ull f = *reinterpret_cast<const ull*>(sGT + k * 66 + r0);
            const float* wr = sW + k * 128 + 2 * c0;
            ulonglong2 wa = *reinterpret_cast<const ulonglong2*>(wr);
            ulonglong2 wb = *reinterpret_cast<const ulonglong2*>(wr + 4);
            ulonglong2 wc = *reinterpret_cast<const ulonglong2*>(wr + 8);
            ulonglong2 wd = *reinterpret_cast<const ulonglong2*>(wr + 12);
            ffma2_(acc2[0], f, wa.x); ffma2_(acc2[1], f, wa.y);
            ffma2_(acc2[2], f, wb.x); ffma2_(acc2[3], f, wb.y);
            ffma2_(acc2[4], f, wc.x); ffma2_(acc2[5], f, wc.y);
            ffma2_(acc2[6], f, wd.x); ffma2_(acc2[7], f, wd.y);
        }
        float og0[8], og1[8];
#pragma unroll
        for (int j = 0; j < 8; j++) {
            int c = c0 + j;
            float2 p = unpk_(acc2[j]);  // rows r0, r0+1
            float bb = __ldg(bng + c), rr2 = __ldg(rm2 + c);
            og0[j] = gatef_(p.x + bb, rr2);
            og1[j] = gatef_(p.y + bb, rr2);
        }
        *reinterpret_cast<float4*>(out + (row0 + r0) * 128 + c0) =
            make_float4(og0[0], og0[1], og0[2], og0[3]);
        *reinterpret_cast<float4*>(out + (row0 + r0) * 128 + c0 + 4) =
            make_float4(og0[4], og0[5], og0[6], og0[7]);
        *reinterpret_cast<float4*>(out + (row0 + r0 + 1) * 128 + c0) =
            make_float4(og1[0], og1[1], og1[2], og1[3]);
        *reinterpret_cast<float4*>(out + (row0 + r0 + 1) * 128 + c0 + 4) =
            make_float4(og1[4], og1[5], og1[6], og1[7]);
    }
    __syncthreads();

    // ---- P4: Wf1T -> sW ----
    copy_w(sW, g_WT[1], tid, 4096);
    __syncthreads();

    // ---- P5: GEMM3 (K=256) -> out[:,64:128] ----
    {
        ull acc[2][4] = {};
        gemm_fuse(sW, sMxd, sM2yd, sMzd, r0, c0, acc);
#pragma unroll
        for (int i = 0; i < 2; i++) {
            float og[8];
#pragma unroll
            for (int j = 0; j < 4; j++) {
                float2 p = unpk_(acc[i][j]);
                int ca = c0 + 2 * j, cb = ca + 1;
                og[2 * j] =
                    gatef_(leakyf_(p.x + __ldg(bf1 + ca)), __ldg(rm2 + 64 + ca));
                og[2 * j + 1] =
                    gatef_(leakyf_(p.y + __ldg(bf1 + cb)), __ldg(rm2 + 64 + cb));
            }
            float* orow = out + (row0 + r0 + i) * 128 + 64 + c0;
            *reinterpret_cast<float4*>(orow) =
                make_float4(og[0], og[1], og[2], og[3]);
            *reinterpret_cast<float4*>(orow + 4) =
                make_float4(og[4], og[5], og[6], og[7]);
        }
    }
}

extern "C" void kernel_launch(void* const* d_in, const int* in_sizes, int n_in,
                              void* d_out, int out_size) {
    const float* a    = (const float*)d_in[0];
    const float* v    = (const float*)d_in[1];
    const float* l    = (const float*)d_in[2];
    const float* pa   = (const float*)d_in[3];
    const float* pv   = (const float*)d_in[4];
    const float* pl   = (const float*)d_in[5];
    const float* mean = (const float*)d_in[6];
    const float* Wa   = (const float*)d_in[7];
    const float* ba   = (const float*)d_in[8];
    const float* Wv   = (const float*)d_in[9];
    const float* bv   = (const float*)d_in[10];
    const float* Wl   = (const float*)d_in[11];
    const float* bl   = (const float*)d_in[12];
    const float* Wap  = (const float*)d_in[13];
    const float* bap  = (const float*)d_in[14];
    const float* Wvp  = (const float*)d_in[15];
    const float* bvp  = (const float*)d_in[16];
    const float* Wlp  = (const float*)d_in[17];
    const float* blp  = (const float*)d_in[18];
    const float* Wf1  = (const float*)d_in[19];
    const float* bf1  = (const float*)d_in[20];
    const float* Wfp1 = (const float*)d_in[21];
    const float* bfp1 = (const float*)d_in[22];
    const float* Wng  = (const float*)d_in[23];
    const float* bng  = (const float*)d_in[24];
    const float* rm1  = (const float*)d_in[25];
    const float* rm2  = (const float*)d_in[26];

    int nrows = in_sizes[0] / 64;
    static int smem_set = 0;
    if (!smem_set) {
        cudaFuncSetAttribute(fusion_main,
                             cudaFuncAttributeMaxDynamicSharedMemorySize,
                             SMEM_FLOATS * 4);
        smem_set = 1;
    }

    setup_kernel<<<64, 256>>>(Wfp1, Wf1, Wng);
    fusion_main<<<nrows / 64, 256, SMEM_FLOATS * 4>>>(
        a, v, l, pa, pv, pl, mean,
        Wa, ba, Wv, bv, Wl, bl,
        Wap, bap, Wvp, bvp, Wlp, blp,
        bf1, bfp1, bng, rm1, rm2, (float*)d_out);
}

// round 6
// speedup vs baseline: 2.3075x; 2.0170x over previous
#include <cuda_runtime.h>

typedef unsigned long long ull;

// Interleaved transposed weights (built per replay by setup_kernel).
// g_WT[i][k*64 + h*32 + g*4 + e]  = W[c][k],  c = g*8 + h*4 + e   (h<2, e<4)
// g_WngTd[k*128 + h*32 + g*4 + p*2 + {0,1}] = Wng[c][k] (dup), c = g*8 + 2h + p
__device__ float g_WT[2][256 * 64];
__device__ float g_WngTd[128 * 128];

__global__ void setup_kernel(const float* __restrict__ Wfp1,
                             const float* __restrict__ Wf1,
                             const float* __restrict__ Wng) {
    int tid = blockIdx.x * blockDim.x + threadIdx.x;
    int stride = gridDim.x * blockDim.x;
    for (int i = tid; i < 64 * 256; i += stride) {
        int c = i >> 8, k = i & 255;
        int g = c >> 3, h = (c >> 2) & 1, e = c & 3;
        int d = k * 64 + h * 32 + g * 4 + e;
        g_WT[0][d] = Wfp1[i];
        g_WT[1][d] = Wf1[i];
    }
    for (int i = tid; i < 64 * 128; i += stride) {
        int c = i >> 7, k = i & 127;
        int g = c >> 3, h = (c & 7) >> 1, p = c & 1;
        float w = Wng[i];
        int d = k * 128 + h * 32 + g * 4 + p * 2;
        g_WngTd[d] = w;
        g_WngTd[d + 1] = w;
    }
}

__device__ __forceinline__ float sigmoidf_(float x) {
    return __fdividef(1.0f, 1.0f + __expf(-x));
}
__device__ __forceinline__ float gatef_(float x, float rm) {
    return x * sigmoidf_(fabsf(x - rm));
}
__device__ __forceinline__ float leakyf_(float x) {
    return x > 0.0f ? x : 0.01f * x;
}
__device__ __forceinline__ void ffma2_(ull& d, ull a, ull b) {
    asm("fma.rn.f32x2 %0, %1, %2, %0;" : "+l"(d) : "l"(a), "l"(b));
}
__device__ __forceinline__ ull fmul2_(ull a, ull b) {
    ull r;
    asm("mul.rn.f32x2 %0, %1, %2;" : "=l"(r) : "l"(a), "l"(b));
    return r;
}
__device__ __forceinline__ float2 unpk_(ull v) {
    float2 r;
    asm("mov.b64 {%0, %1}, %2;" : "=f"(r.x), "=f"(r.y) : "l"(v));
    return r;
}

__device__ __forceinline__ void copy_w(float* __restrict__ dst,
                                       const float* __restrict__ src,
                                       int tid) {
    const float4* s = reinterpret_cast<const float4*>(src);
    float4* d = reinterpret_cast<float4*>(dst);
#pragma unroll
    for (int i = tid; i < 4096; i += 256) d[i] = s[i];
}

// Matvecs + sigmoid + pooling for one branch. Thread (r, q): outputs
// j = q*8..q*8+7 of all 3 modalities for row `row`. FFMA2 over k-pairs.
// Writes duplicated factors into sMxd[8][256], sM2yd[4][256], sMzd[8][256].
__device__ __forceinline__ void matvec_pool(
    const float* __restrict__ x, const float* __restrict__ y,
    const float* __restrict__ z, int row,
    float* __restrict__ sMxd, float* __restrict__ sM2yd,
    float* __restrict__ sMzd,
    const float* __restrict__ Wx, const float* __restrict__ bx,
    const float* __restrict__ Wy, const float* __restrict__ by,
    const float* __restrict__ Wz, const float* __restrict__ bz,
    int r, int q) {
    ull ax[8], ay[8], az[8];
#pragma unroll
    for (int j = 0; j < 8; j++) { ax[j] = 0; ay[j] = 0; az[j] = 0; }
#pragma unroll 2
    for (int k = 0; k < 64; k += 4) {
        ulonglong2 x2 = __ldg(reinterpret_cast<const ulonglong2*>(x + row * 64 + k));
        ulonglong2 y2 = __ldg(reinterpret_cast<const ulonglong2*>(y + row * 64 + k));
        ulonglong2 z2 = __ldg(reinterpret_cast<const ulonglong2*>(z + row * 64 + k));
#pragma unroll
        for (int j = 0; j < 8; j++) {
            int wo = (q * 8 + j) * 64 + k;
            ulonglong2 w0 = __ldg(reinterpret_cast<const ulonglong2*>(Wx + wo));
            ffma2_(ax[j], x2.x, w0.x);
            ffma2_(ax[j], x2.y, w0.y);
            ulonglong2 w1 = __ldg(reinterpret_cast<const ulonglong2*>(Wy + wo));
            ffma2_(ay[j], y2.x, w1.x);
            ffma2_(ay[j], y2.y, w1.y);
            ulonglong2 w2 = __ldg(reinterpret_cast<const ulonglong2*>(Wz + wo));
            ffma2_(az[j], z2.x, w2.x);
            ffma2_(az[j], z2.y, w2.y);
        }
    }
    float hx[8], hy[8], hz[8];
#pragma unroll
    for (int j = 0; j < 8; j++) {
        float2 px = unpk_(ax[j]);
        hx[j] = sigmoidf_(px.x + px.y + __ldg(bx + q * 8 + j));
        float2 py = unpk_(ay[j]);
        hy[j] = sigmoidf_(py.x + py.y + __ldg(by + q * 8 + j));
        float2 pz = unpk_(az[j]);
        hz[j] = sigmoidf_(pz.x + pz.y + __ldg(bz + q * 8 + j));
    }
#pragma unroll
    for (int i = 0; i < 4; i++) {
        float m = fmaxf(hx[2 * i], hx[2 * i + 1]);
        *reinterpret_cast<float2*>(sMxd + (q * 4 + i) * 256 + 2 * r) =
            make_float2(m, m);
        m = fmaxf(hz[2 * i], hz[2 * i + 1]);
        *reinterpret_cast<float2*>(sMzd + (q * 4 + i) * 256 + 2 * r) =
            make_float2(m, m);
    }
#pragma unroll
    for (int i = 0; i < 2; i++) {
        float m = fmaxf(fmaxf(hy[4 * i], hy[4 * i + 1]),
                        fmaxf(hy[4 * i + 2], hy[4 * i + 3]));
        *reinterpret_cast<float2*>(sM2yd + (q * 2 + i) * 256 + 2 * r) =
            make_float2(m, m);
    }
}

// Fusion GEMM, 4 rows x 8 cols per thread, F built on the fly:
// F[k=u*8+t][row] = mx[u>>2]*m2y[u&3]*mz[t].  Weights interleaved in sW.
// acc[i][j]: row r0+i, cols (c0+2j, c0+2j+1) packed.
__device__ __forceinline__ void gemm_fuse(
    const float* __restrict__ sW, const float* __restrict__ sMxd,
    const float* __restrict__ sM2yd, const float* __restrict__ sMzd,
    int r0, int g, ull acc[4][4]) {
#pragma unroll 1
    for (int ix = 0; ix < 8; ix++) {
        ulonglong2 ma = *reinterpret_cast<const ulonglong2*>(sMxd + ix * 256 + 2 * r0);
        ulonglong2 mb = *reinterpret_cast<const ulonglong2*>(sMxd + ix * 256 + 2 * r0 + 4);
#pragma unroll 1
        for (int iy = 0; iy < 4; iy++) {
            ulonglong2 ya = *reinterpret_cast<const ulonglong2*>(sM2yd + iy * 256 + 2 * r0);
            ulonglong2 yb = *reinterpret_cast<const ulonglong2*>(sM2yd + iy * 256 + 2 * r0 + 4);
            ull P0 = fmul2_(ma.x, ya.x);
            ull P1 = fmul2_(ma.y, ya.y);
            ull P2 = fmul2_(mb.x, yb.x);
            ull P3 = fmul2_(mb.y, yb.y);
            const float* wrow = sW + (ix * 4 + iy) * 8 * 64 + g * 4;
#pragma unroll
            for (int t = 0; t < 8; t++) {
                ulonglong2 za = *reinterpret_cast<const ulonglong2*>(sMzd + t * 256 + 2 * r0);
                ulonglong2 zb = *reinterpret_cast<const ulonglong2*>(sMzd + t * 256 + 2 * r0 + 4);
                ulonglong2 w0 = *reinterpret_cast<const ulonglong2*>(wrow + t * 64);
                ulonglong2 w1 = *reinterpret_cast<const ulonglong2*>(wrow + t * 64 + 32);
                ull f0 = fmul2_(P0, za.x);
                ull f1 = fmul2_(P1, za.y);
                ull f2 = fmul2_(P2, zb.x);
                ull f3 = fmul2_(P3, zb.y);
                ffma2_(acc[0][0], f0, w0.x); ffma2_(acc[0][1], f0, w0.y);
                ffma2_(acc[0][2], f0, w1.x); ffma2_(acc[0][3], f0, w1.y);
                ffma2_(acc[1][0], f1, w0.x); ffma2_(acc[1][1], f1, w0.y);
                ffma2_(acc[1][2], f1, w1.x); ffma2_(acc[1][3], f1, w1.y);
                ffma2_(acc[2][0], f2, w0.x); ffma2_(acc[2][1], f2, w0.y);
                ffma2_(acc[2][2], f2, w1.x); ffma2_(acc[2][3], f2, w1.y);
                ffma2_(acc[3][0], f3, w0.x); ffma2_(acc[3][1], f3, w0.y);
                ffma2_(acc[3][2], f3, w1.x); ffma2_(acc[3][3], f3, w1.y);
            }
        }
    }
}

// Shared layout (floats): sWa 0..16384, sWb ..32768, sGT[128][132] ..49664,
// sMxd[8][256] ..51712, sM2yd[4][256] ..52736, sMzd[8][256] ..54784.
#define SMEM_FLOATS 54784

__global__ void __launch_bounds__(256) fusion_main(
    const float* __restrict__ a, const float* __restrict__ v,
    const float* __restrict__ l, const float* __restrict__ pa,
    const float* __restrict__ pv, const float* __restrict__ pl,
    const float* __restrict__ mean,
    const float* __restrict__ Wa, const float* __restrict__ ba,
    const float* __restrict__ Wv, const float* __restrict__ bv,
    const float* __restrict__ Wl, const float* __restrict__ bl,
    const float* __restrict__ Wap, const float* __restrict__ bap,
    const float* __restrict__ Wvp, const float* __restrict__ bvp,
    const float* __restrict__ Wlp, const float* __restrict__ blp,
    const float* __restrict__ bf1, const float* __restrict__ bfp1,
    const float* __restrict__ bng, const float* __restrict__ rm1,
    const float* __restrict__ rm2, float* __restrict__ out) {
    extern __shared__ __align__(16) float smem[];
    float* sWa = smem;
    float* sWb = smem + 16384;
    float* sGT = smem + 32768;
    float* sMxd = smem + 49664;
    float* sM2yd = smem + 51712;
    float* sMzd = smem + 52736;

    const int tid = threadIdx.x;
    const int row0 = blockIdx.x * 128;
    const int r = tid >> 1, q = tid & 1;       // matvec mapping (128 rows)
    const int r0 = (tid >> 3) * 4;             // GEMM row base
    const int g = tid & 7;                     // GEMM col group
    const int c0 = g * 8;

    // ---- P0: weights -> smem; gated mean -> sGT[64..127]; fusion-2 factors
    copy_w(sWa, g_WT[0], tid);
    copy_w(sWb, g_WngTd, tid);
#pragma unroll
    for (int it = 0; it < 32; it++) {
        int i = tid + it * 256;
        int rr = i >> 6, c = i & 63;
        float m = __ldg(mean + (row0 + rr) * 64 + c);
        sGT[(64 + c) * 132 + rr] = gatef_(m, __ldg(rm1 + 64 + c));
    }
    matvec_pool(pa, pv, pl, row0 + r, sMxd, sM2yd, sMzd,
                Wap, bap, Wvp, bvp, Wlp, blp, r, q);
    __syncthreads();

    // ---- P1: GEMM1 (K=256) -> gate -> sGT[0..63] ----
    {
        ull acc[4][4] = {};
        gemm_fuse(sWa, sMxd, sM2yd, sMzd, r0, g, acc);
#pragma unroll
        for (int j = 0; j < 4; j++) {
            int ca = c0 + 2 * j, cb = ca + 1;
            float ba_ = __ldg(bfp1 + ca), bb_ = __ldg(bfp1 + cb);
            float ra_ = __ldg(rm1 + ca), rb_ = __ldg(rm1 + cb);
#pragma unroll
            for (int i = 0; i < 4; i++) {
                float2 p = unpk_(acc[i][j]);
                sGT[ca * 132 + r0 + i] = gatef_(leakyf_(p.x + ba_), ra_);
                sGT[cb * 132 + r0 + i] = gatef_(leakyf_(p.y + bb_), rb_);
            }
        }
    }
    __syncthreads();

    // ---- P2: reload sWa=Wf1T; fusion-1 factors; GEMM2 -> out[:,0:64] ----
    copy_w(sWa, g_WT[1], tid);
    matvec_pool(a, v, l, row0 + r, sMxd, sM2yd, sMzd,
                Wa, ba, Wv, bv, Wl, bl, r, q);
    {
        ull acc2[2][8] = {};
#pragma unroll 4
        for (int k = 0; k < 128; k++) {
            ulonglong2 ff = *reinterpret_cast<const ulonglong2*>(sGT + k * 132 + r0);
            const float* wr = sWb + k * 128 + g * 4;
            ulonglong2 w0 = *reinterpret_cast<const ulonglong2*>(wr);
            ulonglong2 w1 = *reinterpret_cast<const ulonglong2*>(wr + 32);
            ulonglong2 w2 = *reinterpret_cast<const ulonglong2*>(wr + 64);
            ulonglong2 w3 = *reinterpret_cast<const ulonglong2*>(wr + 96);
            ffma2_(acc2[0][0], ff.x, w0.x); ffma2_(acc2[0][1], ff.x, w0.y);
            ffma2_(acc2[0][2], ff.x, w1.x); ffma2_(acc2[0][3], ff.x, w1.y);
            ffma2_(acc2[0][4], ff.x, w2.x); ffma2_(acc2[0][5], ff.x, w2.y);
            ffma2_(acc2[0][6], ff.x, w3.x); ffma2_(acc2[0][7], ff.x, w3.y);
            ffma2_(acc2[1][0], ff.y, w0.x); ffma2_(acc2[1][1], ff.y, w0.y);
            ffma2_(acc2[1][2], ff.y, w1.x); ffma2_(acc2[1][3], ff.y, w1.y);
            ffma2_(acc2[1][4], ff.y, w2.x); ffma2_(acc2[1][5], ff.y, w2.y);
            ffma2_(acc2[1][6], ff.y, w3.x); ffma2_(acc2[1][7], ff.y, w3.y);
        }
#pragma unroll
        for (int rp = 0; rp < 2; rp++) {
            float oe[8], oo[8];
#pragma unroll
            for (int j = 0; j < 8; j++) {
                int c = c0 + j;
                float bb = __ldg(bng + c), rr2 = __ldg(rm2 + c);
                float2 p = unpk_(acc2[rp][j]);
                oe[j] = gatef_(p.x + bb, rr2);
                oo[j] = gatef_(p.y + bb, rr2);
            }
            float* oreven = out + (row0 + r0 + 2 * rp) * 128 + c0;
            float* orodd = out + (row0 + r0 + 2 * rp + 1) * 128 + c0;
            *reinterpret_cast<float4*>(oreven) = make_float4(oe[0], oe[1], oe[2], oe[3]);
            *reinterpret_cast<float4*>(oreven + 4) = make_float4(oe[4], oe[5], oe[6], oe[7]);
            *reinterpret_cast<float4*>(orodd) = make_float4(oo[0], oo[1], oo[2], oo[3]);
            *reinterpret_cast<float4*>(orodd + 4) = make_float4(oo[4], oo[5], oo[6], oo[7]);
        }
    }
    __syncthreads();

    // ---- P3: GEMM3 (K=256) -> out[:,64:128] ----
    {
        ull acc[4][4] = {};
        gemm_fuse(sWa, sMxd, sM2yd, sMzd, r0, g, acc);
#pragma unroll
        for (int i = 0; i < 4; i++) {
            float og[8];
#pragma unroll
            for (int j = 0; j < 4; j++) {
                int ca = c0 + 2 * j, cb = ca + 1;
                float2 p = unpk_(acc[i][j]);
                og[2 * j] = gatef_(leakyf_(p.x + __ldg(bf1 + ca)),
                                   __ldg(rm2 + 64 + ca));
                og[2 * j + 1] = gatef_(leakyf_(p.y + __ldg(bf1 + cb)),
                                       __ldg(rm2 + 64 + cb));
            }
            float* orow = out + (row0 + r0 + i) * 128 + 64 + c0;
            *reinterpret_cast<float4*>(orow) = make_float4(og[0], og[1], og[2], og[3]);
            *reinterpret_cast<float4*>(orow + 4) = make_float4(og[4], og[5], og[6], og[7]);
        }
    }
}

extern "C" void kernel_launch(void* const* d_in, const int* in_sizes, int n_in,
                              void* d_out, int out_size) {
    const float* a    = (const float*)d_in[0];
    const float* v    = (const float*)d_in[1];
    const float* l    = (const float*)d_in[2];
    const float* pa   = (const float*)d_in[3];
    const float* pv   = (const float*)d_in[4];
    const float* pl   = (const float*)d_in[5];
    const float* mean = (const float*)d_in[6];
    const float* Wa   = (const float*)d_in[7];
    const float* ba   = (const float*)d_in[8];
    const float* Wv   = (const float*)d_in[9];
    const float* bv   = (const float*)d_in[10];
    const float* Wl   = (const float*)d_in[11];
    const float* bl   = (const float*)d_in[12];
    const float* Wap  = (const float*)d_in[13];
    const float* bap  = (const float*)d_in[14];
    const float* Wvp  = (const float*)d_in[15];
    const float* bvp  = (const float*)d_in[16];
    const float* Wlp  = (const float*)d_in[17];
    const float* blp  = (const float*)d_in[18];
    const float* Wf1  = (const float*)d_in[19];
    const float* bf1  = (const float*)d_in[20];
    const float* Wfp1 = (const float*)d_in[21];
    const float* bfp1 = (const float*)d_in[22];
    const float* Wng  = (const float*)d_in[23];
    const float* bng  = (const float*)d_in[24];
    const float* rm1  = (const float*)d_in[25];
    const float* rm2  = (const float*)d_in[26];

    int nrows = in_sizes[0] / 64;
    static int smem_set = 0;
    if (!smem_set) {
        cudaFuncSetAttribute(fusion_main,
                             cudaFuncAttributeMaxDynamicSharedMemorySize,
                             SMEM_FLOATS * 4);
        smem_set = 1;
    }

    setup_kernel<<<64, 256>>>(Wfp1, Wf1, Wng);
    fusion_main<<<nrows / 128, 256, SMEM_FLOATS * 4>>>(
        a, v, l, pa, pv, pl, mean,
        Wa, ba, Wv, bv, Wl, bl,
        Wap, bap, Wvp, bvp, Wlp, blp,
        bf1, bfp1, bng, rm1, rm2, (float*)d_out);
}